// round 13
// baseline (speedup 1.0000x reference)
#include <cuda_runtime.h>
#include <cuda_fp16.h>
#include <math.h>
#include <stdint.h>

#define B_    64
#define S_    4096
#define E_    266
#define HID_  512
#define NH_   128
#define M_    (B_ * NH_)   /* 8192 rows */
#define KC_   32           /* K chunk */
#define NCH_  16           /* chunks per pass */
#define SPADB_ 80          /* padded smem row stride in BYTES (both passes) */
#define BM_   256
#define BN_   128
#define NT_   512          /* 16 warps, warp grid 4x4, warp tile 64x32 */

#define OFF_B_    (BM_ * SPADB_)            /* 20480 */
#define STAGE_B   (OFF_B_ + BN_ * SPADB_)   /* 30720 */
#define NSTAGE_   3
#define SMEM_DYN  (NSTAGE_ * STAGE_B)       /* 92160 */

#define SCALE_UP   2048.0f
#define SCALE_DN   (1.0f / 2048.0f)

// ---------------- device scratch ----------------
__device__ __align__(16) __half g_ahi[2][M_ * HID_];              // fp16 hi activations
__device__ __align__(16) unsigned char g_ac8[2][M_ * HID_ * 2];   // [chunk:64B = Ahi8(32)|Alo'(32)]
__device__ __align__(16) __half g_wthi[3][HID_ * HID_];           // W^T fp16 hi
__device__ __align__(16) unsigned char g_wc8[3][HID_ * HID_ * 2]; // [chunk:64B = Blo'(32)|Bhi8(32)]
__device__ float g_zw[B_ * HID_];
__device__ float g_ew[NH_ * HID_];
__device__ float g_sinc[M_];
__device__ float g_cosc[M_];

__device__ __forceinline__ float silu(float v) {
    return __fdividef(v, 1.0f + __expf(-v));
}
__device__ __forceinline__ uint32_t smem_u32(const void* p) {
    uint32_t a;
    asm("{ .reg .u64 t; cvta.to.shared.u64 t, %1; cvt.u32.u64 %0, t; }" : "=r"(a) : "l"(p));
    return a;
}
__device__ __forceinline__ void cp16(uint32_t sm, const void* g) {
    asm volatile("cp.async.cg.shared.global [%0], [%1], 16;" :: "r"(sm), "l"(g));
}
__device__ __forceinline__ void cp_commit() {
    asm volatile("cp.async.commit_group;" ::: "memory");
}
template <int N>
__device__ __forceinline__ void cp_wait() {
    asm volatile("cp.async.wait_group %0;" :: "n"(N) : "memory");
}
__device__ __forceinline__ void ldsm_x4(uint32_t* r, uint32_t addr) {
    asm volatile("ldmatrix.sync.aligned.m8n8.x4.shared.b16 {%0,%1,%2,%3}, [%4];"
                 : "=r"(r[0]), "=r"(r[1]), "=r"(r[2]), "=r"(r[3]) : "r"(addr));
}
__device__ __forceinline__ void mma_f16(float* c, const uint32_t* a, uint32_t b0, uint32_t b1) {
    asm volatile("mma.sync.aligned.m16n8k16.row.col.f32.f16.f16.f32 "
                 "{%0,%1,%2,%3}, {%4,%5,%6,%7}, {%8,%9}, {%0,%1,%2,%3};"
                 : "+f"(c[0]), "+f"(c[1]), "+f"(c[2]), "+f"(c[3])
                 : "r"(a[0]), "r"(a[1]), "r"(a[2]), "r"(a[3]), "r"(b0), "r"(b1));
}
__device__ __forceinline__ void mma_fp8(float* c, const uint32_t* a, uint32_t b0, uint32_t b1) {
    asm volatile("mma.sync.aligned.m16n8k32.row.col.f32.e4m3.e4m3.f32 "
                 "{%0,%1,%2,%3}, {%4,%5,%6,%7}, {%8,%9}, {%0,%1,%2,%3};"
                 : "+f"(c[0]), "+f"(c[1]), "+f"(c[2]), "+f"(c[3])
                 : "r"(a[0]), "r"(a[1]), "r"(a[2]), "r"(a[3]), "r"(b0), "r"(b1));
}
// pack 2 floats to e4m3x2: low byte = vlo, high byte = vhi
__device__ __forceinline__ unsigned short cvt_e4m3x2(float vhi, float vlo) {
    unsigned short r;
    asm("cvt.rn.satfinite.e4m3x2.f32 %0, %1, %2;" : "=h"(r) : "f"(vhi), "f"(vlo));
    return r;
}

// ---------------- fused prep: weight transpose/split + zw/ew + coeff init ----
__global__ void k_prep(const float* __restrict__ w_h,
                       const float* __restrict__ z, const float* __restrict__ emb,
                       const float* __restrict__ w_in, const float* __restrict__ b_in,
                       const float* __restrict__ b_out) {
    if (blockIdx.x < 768) {
        __shared__ float t[32][33];
        const int idx = blockIdx.x;
        const int l = idx >> 8;
        const int rem = idx & 255;
        const int k0 = (rem >> 4) * 32, n0 = (rem & 15) * 32;
        const int tx = threadIdx.x & 31, ty = threadIdx.x >> 5;
        const float* W = w_h + (size_t)l * HID_ * HID_;
        for (int i = ty; i < 32; i += 8)
            t[i][tx] = W[(size_t)(k0 + i) * HID_ + n0 + tx];
        __syncthreads();
        for (int i = ty; i < 32; i += 8) {
            const float v = t[tx][i];
            const __half hi = __float2half_rn(v);
            const float hif = __half2float(hi);
            const float lo = v - hif;
            const int n = n0 + i;
            const int k = k0 + tx;
            g_wthi[l][(size_t)n * HID_ + k] = hi;
            // corr B layout: chunk c: [Blo'(32) | Bhi8(32)]
            const size_t b8 = (size_t)n * (2 * HID_) + (k >> 5) * 64 + (k & 31);
            unsigned short p_lo = cvt_e4m3x2(0.f, lo * SCALE_UP);
            unsigned short p_hi = cvt_e4m3x2(0.f, hif);
            g_wc8[l][b8]      = (unsigned char)(p_lo & 0xFF);
            g_wc8[l][b8 + 32] = (unsigned char)(p_hi & 0xFF);
        }
    } else {
        __shared__ float vr[E_];
        const int idx2 = blockIdx.x - 768;
        const int dblk = idx2 & 1;
        const int y = idx2 >> 1;
        const bool is_z = (y < B_);
        const int row = is_z ? y : y - B_;
        const float* src = (is_z ? z : emb) + (size_t)row * E_;
        for (int e = threadIdx.x; e < E_; e += blockDim.x) vr[e] = src[e];
        __syncthreads();
        const int d = dblk * 256 + threadIdx.x;
        float acc = is_z ? 0.f : b_in[d];
        #pragma unroll 2
        for (int e = 0; e < E_; e++) acc = fmaf(vr[e], __ldg(w_in + e * HID_ + d), acc);
        if (is_z) g_zw[row * HID_ + d] = acc;
        else      g_ew[row * HID_ + d] = acc;
        if (!is_z && row < 16) {
            const int i = row * HID_ + d;
            g_sinc[i] = b_out[0];
            g_cosc[i] = b_out[1];
        }
    }
}

// ---------------- h0: A0 = silu(zw[b]+ew[h]) -> fp16 + fp8 pair ----------------
// grid 8192 blocks x 128 threads; thread handles 4 consecutive cols
__global__ void k_h0() {
    const int row = blockIdx.x;
    const int d4 = threadIdx.x * 4;
    const int bb = row >> 7;
    const int hh = row & (NH_ - 1);
    const float4 zv = *(const float4*)(g_zw + bb * HID_ + d4);
    const float4 ev = *(const float4*)(g_ew + hh * HID_ + d4);
    float v[4];
    v[0] = silu(zv.x + ev.x); v[1] = silu(zv.y + ev.y);
    v[2] = silu(zv.z + ev.z); v[3] = silu(zv.w + ev.w);
    __half h[4];
    float hf[4], lo[4];
    #pragma unroll
    for (int i = 0; i < 4; i++) {
        h[i] = __float2half_rn(v[i]);
        hf[i] = __half2float(h[i]);
        lo[i] = v[i] - hf[i];
    }
    // fp16 store (8B)
    uint2 hp;
    hp.x = ((uint32_t)__half_as_ushort(h[1]) << 16) | __half_as_ushort(h[0]);
    hp.y = ((uint32_t)__half_as_ushort(h[3]) << 16) | __half_as_ushort(h[2]);
    *(uint2*)(&g_ahi[0][(size_t)row * HID_ + d4]) = hp;
    // fp8 stores: A layout chunk c: [Ahi8(32) | Alo'(32)]
    const size_t base = (size_t)row * (2 * HID_) + (d4 >> 5) * 64 + (d4 & 31);
    uint32_t hi8 = ((uint32_t)cvt_e4m3x2(hf[3], hf[2]) << 16) | cvt_e4m3x2(hf[1], hf[0]);
    uint32_t lo8 = ((uint32_t)cvt_e4m3x2(lo[3] * SCALE_UP, lo[2] * SCALE_UP) << 16)
                 | cvt_e4m3x2(lo[1] * SCALE_UP, lo[0] * SCALE_UP);
    *(uint32_t*)(&g_ac8[0][base]) = hi8;
    *(uint32_t*)(&g_ac8[0][base + 32]) = lo8;
}

// ---------------- MLP GEMM: fp16 main pass + fp8 correction pass ----------------
// acc_final = acc_main*2^11 + corr'(=2^11*corr); epilogue scales by 2^-11.
// MODE 0: writes next-layer fp16 + fp8 operands. MODE 2: fused w_out projection.
template <int MODE>
__global__ void __launch_bounds__(NT_, 1) k_mma_gemm(int layer, int src, int dst,
                                                     const float* __restrict__ bias,
                                                     const float* __restrict__ w_out) {
    extern __shared__ char smem[];
    const int tid = threadIdx.x;
    const int wid = tid >> 5;
    const int lane = tid & 31;
    const int wm = wid & 3;        // 4 warp-rows of 64
    const int wn = wid >> 2;       // 4 warp-cols of 32
    const int m0 = blockIdx.y * BM_;
    const int n0 = blockIdx.x * BN_;

    const __half* __restrict__ Ahi = g_ahi[src];
    const unsigned char* __restrict__ Ac8 = g_ac8[src];
    const __half* __restrict__ Wthi = g_wthi[layer];
    const unsigned char* __restrict__ Wc8 = g_wc8[layer];
    __half* __restrict__ Dhi = g_ahi[dst];
    unsigned char* __restrict__ Dc8 = g_ac8[dst];

    const uint32_t smb = smem_u32(smem);

    auto stage_load = [&](int c) {
        const uint32_t sbu = smb + (c % NSTAGE_) * STAGE_B;
        if (c < NCH_) {
            const int k0 = c * KC_;
            #pragma unroll
            for (int i = 0; i < 2; i++) {           // A fp16: 1024 cp16
                const int idx = tid + i * NT_;
                const int r = idx >> 2;
                const int c16 = idx & 3;
                cp16(sbu + r * SPADB_ + c16 * 16,
                     Ahi + (size_t)(m0 + r) * HID_ + k0 + c16 * 8);
            }
            {                                        // B fp16: 512 cp16
                const int r = tid >> 2;
                const int c16 = tid & 3;
                cp16(sbu + OFF_B_ + r * SPADB_ + c16 * 16,
                     Wthi + (size_t)(n0 + r) * HID_ + k0 + c16 * 8);
            }
        } else {
            const int cc = c - NCH_;
            #pragma unroll
            for (int i = 0; i < 2; i++) {           // A fp8: 1024 cp16
                const int idx = tid + i * NT_;
                const int r = idx >> 2;
                const int c16 = idx & 3;
                cp16(sbu + r * SPADB_ + c16 * 16,
                     Ac8 + (size_t)(m0 + r) * (2 * HID_) + cc * 64 + c16 * 16);
            }
            {                                        // B fp8: 512 cp16
                const int r = tid >> 2;
                const int c16 = tid & 3;
                cp16(sbu + OFF_B_ + r * SPADB_ + c16 * 16,
                     Wc8 + (size_t)(n0 + r) * (2 * HID_) + cc * 64 + c16 * 16);
            }
        }
        cp_commit();
    };

    float acc[4][4][4];
    #pragma unroll
    for (int i = 0; i < 4; i++)
        #pragma unroll
        for (int j = 0; j < 4; j++)
            #pragma unroll
            for (int q = 0; q < 4; q++) acc[i][j][q] = 0.f;

    // pass-1 (fp16, b16 units) addressing
    const int arow = wm * 64 + (lane & 15);
    const int acol = (lane >> 4) << 3;               // b16 cols 0/8
    const int brow = wn * 32 + ((lane >> 4) & 1) * 8 + (lane & 7);
    const int bcol = ((lane >> 3) & 1) * 8;
    // pass-2 (fp8, byte units) addressing
    const int a8row = wm * 64 + (lane & 15);
    const int a8byte = (lane >> 4) * 16;
    const int b8row = wn * 32 + (lane & 15);
    const int b8byte = (lane >> 4) * 16;

    stage_load(0);

    for (int c = 0; c < 2 * NCH_; c++) {
        if (c + 1 < 2 * NCH_) {
            stage_load(c + 1);
            cp_wait<1>();
        } else {
            cp_wait<0>();
        }
        __syncthreads();

        if (c == NCH_) {  // switch to correction pass: scale accumulators up
            #pragma unroll
            for (int i = 0; i < 4; i++)
                #pragma unroll
                for (int j = 0; j < 4; j++)
                    #pragma unroll
                    for (int q = 0; q < 4; q++) acc[i][j][q] *= SCALE_UP;
        }

        const uint32_t sbu = smb + (c % NSTAGE_) * STAGE_B;
        const uint32_t aB = sbu, bB = sbu + OFF_B_;

        if (c < NCH_) {
            // fp16 main pass
            #pragma unroll
            for (int ks = 0; ks < 2; ks++) {
                const int kc = ks * 16;
                uint32_t bh[8];
                #pragma unroll
                for (int np = 0; np < 2; np++) {
                    const uint32_t bo = (uint32_t)(brow + np * 16) * SPADB_ + (bcol + kc) * 2;
                    ldsm_x4(bh + np * 4, bB + bo);
                }
                #pragma unroll
                for (int mt = 0; mt < 4; mt++) {
                    const uint32_t ao = (uint32_t)(arow + mt * 16) * SPADB_ + (acol + kc) * 2;
                    uint32_t ah[4];
                    ldsm_x4(ah, aB + ao);
                    #pragma unroll
                    for (int nt = 0; nt < 4; nt++)
                        mma_f16(acc[mt][nt], ah, bh[nt * 2], bh[nt * 2 + 1]);
                }
            }
        } else {
            // fp8 correction pass (k32; 64 bytes per row = 2 k32 steps)
            #pragma unroll
            for (int ks = 0; ks < 2; ks++) {
                const int kb = ks * 32;
                uint32_t b8[8];
                #pragma unroll
                for (int np = 0; np < 2; np++) {
                    const uint32_t bo = (uint32_t)(b8row + np * 16) * SPADB_ + b8byte + kb;
                    ldsm_x4(b8 + np * 4, bB + bo);
                }
                #pragma unroll
                for (int mt = 0; mt < 4; mt++) {
                    const uint32_t ao = (uint32_t)(a8row + mt * 16) * SPADB_ + a8byte + kb;
                    uint32_t a8[4];
                    ldsm_x4(a8, aB + ao);
                    #pragma unroll
                    for (int nt = 0; nt < 4; nt++) {
                        const int np = nt >> 1, sub = nt & 1;
                        mma_fp8(acc[mt][nt], a8, b8[np * 4 + sub], b8[np * 4 + sub + 2]);
                    }
                }
            }
        }
    }

    // ---- epilogue ----
    const int g = lane >> 2;
    const int cpair = (lane & 3) * 2;

    if (MODE != 2) {
        #pragma unroll
        for (int mt = 0; mt < 4; mt++) {
            #pragma unroll
            for (int nt = 0; nt < 4; nt++) {
                const int row = m0 + wm * 64 + mt * 16 + g;
                const int col = n0 + wn * 32 + nt * 8 + cpair;
                const float b0 = __ldg(bias + col);
                const float b1 = __ldg(bias + col + 1);
                #pragma unroll
                for (int half = 0; half < 2; half++) {
                    const int r = row + half * 8;
                    const float v0 = silu(acc[mt][nt][half * 2 + 0] * SCALE_DN + b0);
                    const float v1 = silu(acc[mt][nt][half * 2 + 1] * SCALE_DN + b1);
                    const __half h0 = __float2half_rn(v0);
                    const __half h1 = __float2half_rn(v1);
                    const float hf0 = __half2float(h0);
                    const float hf1 = __half2float(h1);
                    const uint32_t hp = ((uint32_t)__half_as_ushort(h1) << 16)
                                      | __half_as_ushort(h0);
                    *(uint32_t*)(Dhi + (size_t)r * HID_ + col) = hp;
                    const size_t base = (size_t)r * (2 * HID_) + (col >> 5) * 64 + (col & 31);
                    *(unsigned short*)(Dc8 + base) = cvt_e4m3x2(hf1, hf0);
                    *(unsigned short*)(Dc8 + base + 32) =
                        cvt_e4m3x2((v1 - hf1) * SCALE_UP, (v0 - hf0) * SCALE_UP);
                }
            }
        }
    } else {
        #pragma unroll
        for (int mt = 0; mt < 4; mt++) {
            #pragma unroll
            for (int half = 0; half < 2; half++) {
                float s = 0.f, cs = 0.f;
                #pragma unroll
                for (int nt = 0; nt < 4; nt++) {
                    const int col = n0 + wn * 32 + nt * 8 + cpair;
                    const float b0 = __ldg(bias + col);
                    const float b1 = __ldg(bias + col + 1);
                    const float v0 = silu(acc[mt][nt][half * 2 + 0] * SCALE_DN + b0);
                    const float v1 = silu(acc[mt][nt][half * 2 + 1] * SCALE_DN + b1);
                    s  = fmaf(v0, __ldg(w_out + 2 * col + 0), s);
                    cs = fmaf(v0, __ldg(w_out + 2 * col + 1), cs);
                    s  = fmaf(v1, __ldg(w_out + 2 * col + 2), s);
                    cs = fmaf(v1, __ldg(w_out + 2 * col + 3), cs);
                }
                s  += __shfl_xor_sync(0xffffffffu, s, 1);
                s  += __shfl_xor_sync(0xffffffffu, s, 2);
                cs += __shfl_xor_sync(0xffffffffu, cs, 1);
                cs += __shfl_xor_sync(0xffffffffu, cs, 2);
                if ((lane & 3) == 0) {
                    const int row = m0 + wm * 64 + mt * 16 + g + half * 8;
                    atomicAdd(&g_sinc[row], s);
                    atomicAdd(&g_cosc[row], cs);
                }
            }
        }
    }
}

// ---------------- synthesis: 2-chain integer-frequency recurrence ----------------
__global__ void k_synth(const float* __restrict__ tx, float* __restrict__ out) {
    __shared__ float sc[NH_], cc[NH_];
    const int b = blockIdx.y;
    if (threadIdx.x < NH_) {
        sc[threadIdx.x] = g_sinc[b * NH_ + threadIdx.x];
        cc[threadIdx.x] = g_cosc[b * NH_ + threadIdx.x];
    }
    __syncthreads();
    const int sI = blockIdx.x * blockDim.x + threadIdx.x;
    const float xv = tx[b * S_ + sI];
    const float th = 6.28318530717958647692f * xv;
    float s1, c1;
    sincosf(th, &s1, &c1);
    const float c2 = c1 * c1 - s1 * s1;
    const float s2 = 2.f * s1 * c1;
    float ca = c1, sa = s1;
    float cb = c2, sb = s2;
    float acc0 = fmaf(cc[0], ca, sc[0] * sa);
    float acc1 = fmaf(cc[1], cb, sc[1] * sb);
    #pragma unroll 4
    for (int i = 1; i < 64; i++) {
        const float can = ca * c2 - sa * s2;
        const float san = sa * c2 + ca * s2;
        ca = can; sa = san;
        const float cbn = cb * c2 - sb * s2;
        const float sbn = sb * c2 + cb * s2;
        cb = cbn; sb = sbn;
        acc0 = fmaf(cc[2 * i], ca, acc0);
        acc0 = fmaf(sc[2 * i], sa, acc0);
        acc1 = fmaf(cc[2 * i + 1], cb, acc1);
        acc1 = fmaf(sc[2 * i + 1], sb, acc1);
    }
    out[b * S_ + sI] = acc0 + acc1;
}

// ---------------- launcher ----------------
extern "C" void kernel_launch(void* const* d_in, const int* in_sizes, int n_in,
                              void* d_out, int out_size) {
    const float* target_x = (const float*)d_in[0];
    const float* z        = (const float*)d_in[1];
    /* d_in[2] = x, unused by the reference */
    const float* emb      = (const float*)d_in[3];
    const float* w_in     = (const float*)d_in[4];
    const float* b_in     = (const float*)d_in[5];
    const float* w_h      = (const float*)d_in[6];
    const float* b_h      = (const float*)d_in[7];
    const float* w_out    = (const float*)d_in[8];
    const float* b_out    = (const float*)d_in[9];
    float* out = (float*)d_out;

    cudaFuncSetAttribute(k_mma_gemm<0>, cudaFuncAttributeMaxDynamicSharedMemorySize, SMEM_DYN);
    cudaFuncSetAttribute(k_mma_gemm<2>, cudaFuncAttributeMaxDynamicSharedMemorySize, SMEM_DYN);

    k_prep<<<1152, 256>>>(w_h, z, emb, w_in, b_in, b_out);
    k_h0<<<M_, 128>>>();

    k_mma_gemm<0><<<dim3(HID_ / BN_, M_ / BM_), NT_, SMEM_DYN>>>(0, 0, 1, b_h + 0 * HID_, w_out);
    k_mma_gemm<0><<<dim3(HID_ / BN_, M_ / BM_), NT_, SMEM_DYN>>>(1, 1, 0, b_h + 1 * HID_, w_out);
    k_mma_gemm<2><<<dim3(HID_ / BN_, M_ / BM_), NT_, SMEM_DYN>>>(2, 0, 1, b_h + 2 * HID_, w_out);

    k_synth<<<dim3(S_ / 256, B_), 256>>>(target_x, out);
}

// round 14
// speedup vs baseline: 1.0796x; 1.0796x over previous
#include <cuda_runtime.h>
#include <cuda_bf16.h>
#include <math.h>
#include <stdint.h>

#define B_    64
#define S_    4096
#define E_    266
#define HID_  512
#define NH_   128
#define M_    (B_ * NH_)   /* 8192 rows */
#define KC_   32           /* K chunk */
#define NCH_  (HID_ / KC_) /* 16 chunks */
#define SPAD_ 40           /* padded smem row stride in bf16 */
#define BM_   256          /* CTA tile M */
#define BN_   128          /* CTA tile N */
#define NT_   512          /* 16 warps, warp grid 4x4, warp tile 64x32 */

#define ROWB_     (SPAD_ * 2)                       /* 80 B */
#define OFF_AH    0
#define OFF_AL    (BM_ * ROWB_)                     /* 20480 */
#define OFF_BH    (2 * BM_ * ROWB_)                 /* 40960 */
#define OFF_BL    (2 * BM_ * ROWB_ + BN_ * ROWB_)   /* 51200 */
#define STAGE_B   (2 * BM_ * ROWB_ + 2 * BN_ * ROWB_) /* 61440 */
#define NSTAGE_   3
#define SMEM_DYN  (NSTAGE_ * STAGE_B)               /* 184320 */

__device__ __align__(16) __nv_bfloat16 g_ahi[2][M_ * HID_];
__device__ __align__(16) __nv_bfloat16 g_alo[2][M_ * HID_];
__device__ __align__(16) __nv_bfloat16 g_wthi[3][HID_ * HID_];
__device__ __align__(16) __nv_bfloat16 g_wtlo[3][HID_ * HID_];
__device__ float g_zw[B_ * HID_];
__device__ float g_ew[NH_ * HID_];
__device__ float g_sinc[M_];
__device__ float g_cosc[M_];
__device__ int   g_cnt[M_ / BM_];   /* per-m-stripe completion counters */

__device__ __forceinline__ float silu(float v) {
    return __fdividef(v, 1.0f + __expf(-v));
}
__device__ __forceinline__ uint32_t smem_u32(const void* p) {
    uint32_t a;
    asm("{ .reg .u64 t; cvta.to.shared.u64 t, %1; cvt.u32.u64 %0, t; }" : "=r"(a) : "l"(p));
    return a;
}
__device__ __forceinline__ void cp16(uint32_t sm, const void* g) {
    asm volatile("cp.async.cg.shared.global [%0], [%1], 16;" :: "r"(sm), "l"(g));
}
__device__ __forceinline__ void cp_commit() {
    asm volatile("cp.async.commit_group;" ::: "memory");
}
template <int N>
__device__ __forceinline__ void cp_wait() {
    asm volatile("cp.async.wait_group %0;" :: "n"(N) : "memory");
}
__device__ __forceinline__ void ldsm_x4(uint32_t* r, uint32_t addr) {
    asm volatile("ldmatrix.sync.aligned.m8n8.x4.shared.b16 {%0,%1,%2,%3}, [%4];"
                 : "=r"(r[0]), "=r"(r[1]), "=r"(r[2]), "=r"(r[3]) : "r"(addr));
}
__device__ __forceinline__ void mma_bf16(float* c, const uint32_t* a, const uint32_t* b) {
    asm volatile("mma.sync.aligned.m16n8k16.row.col.f32.bf16.bf16.f32 "
                 "{%0,%1,%2,%3}, {%4,%5,%6,%7}, {%8,%9}, {%0,%1,%2,%3};"
                 : "+f"(c[0]), "+f"(c[1]), "+f"(c[2]), "+f"(c[3])
                 : "r"(a[0]), "r"(a[1]), "r"(a[2]), "r"(a[3]), "r"(b[0]), "r"(b[1]));
}
__device__ __forceinline__ void split_store(char* sm_hi, char* sm_lo, int off,
                                            float v0, float v1, float v2, float v3) {
    const __nv_bfloat16 h0 = __float2bfloat16(v0), h1 = __float2bfloat16(v1);
    const __nv_bfloat16 h2 = __float2bfloat16(v2), h3 = __float2bfloat16(v3);
    const __nv_bfloat16 l0 = __float2bfloat16(v0 - __bfloat162float(h0));
    const __nv_bfloat16 l1 = __float2bfloat16(v1 - __bfloat162float(h1));
    const __nv_bfloat16 l2 = __float2bfloat16(v2 - __bfloat162float(h2));
    const __nv_bfloat16 l3 = __float2bfloat16(v3 - __bfloat162float(h3));
    ushort4 ph, pl;
    ph.x = __bfloat16_as_ushort(h0); ph.y = __bfloat16_as_ushort(h1);
    ph.z = __bfloat16_as_ushort(h2); ph.w = __bfloat16_as_ushort(h3);
    pl.x = __bfloat16_as_ushort(l0); pl.y = __bfloat16_as_ushort(l1);
    pl.z = __bfloat16_as_ushort(l2); pl.w = __bfloat16_as_ushort(l3);
    *(ushort4*)(sm_hi + off) = ph;
    *(ushort4*)(sm_lo + off) = pl;
}

// ---------------- fused prep: weight transpose/split + zw/ew + coeff init ----
__global__ void k_prep(const float* __restrict__ w_h,
                       const float* __restrict__ z, const float* __restrict__ emb,
                       const float* __restrict__ w_in, const float* __restrict__ b_in,
                       const float* __restrict__ b_out) {
    if (blockIdx.x < 768) {
        __shared__ float t[32][33];
        const int idx = blockIdx.x;
        const int l = idx >> 8;
        const int rem = idx & 255;
        const int k0 = (rem >> 4) * 32, n0 = (rem & 15) * 32;
        const int tx = threadIdx.x & 31, ty = threadIdx.x >> 5;
        const float* W = w_h + (size_t)l * HID_ * HID_;
        for (int i = ty; i < 32; i += 8)
            t[i][tx] = W[(size_t)(k0 + i) * HID_ + n0 + tx];
        __syncthreads();
        for (int i = ty; i < 32; i += 8) {
            const float v = t[tx][i];
            const __nv_bfloat16 hi = __float2bfloat16(v);
            const __nv_bfloat16 lo = __float2bfloat16(v - __bfloat162float(hi));
            g_wthi[l][(size_t)(n0 + i) * HID_ + k0 + tx] = hi;
            g_wtlo[l][(size_t)(n0 + i) * HID_ + k0 + tx] = lo;
        }
    } else {
        __shared__ float vr[E_];
        const int idx2 = blockIdx.x - 768;
        if (idx2 == 0 && threadIdx.x < M_ / BM_) g_cnt[threadIdx.x] = 0;
        const int dblk = idx2 & 1;
        const int y = idx2 >> 1;
        const bool is_z = (y < B_);
        const int row = is_z ? y : y - B_;
        const float* src = (is_z ? z : emb) + (size_t)row * E_;
        for (int e = threadIdx.x; e < E_; e += blockDim.x) vr[e] = src[e];
        __syncthreads();
        const int d = dblk * 256 + threadIdx.x;
        float acc = is_z ? 0.f : b_in[d];
        #pragma unroll 2
        for (int e = 0; e < E_; e++) acc = fmaf(vr[e], __ldg(w_in + e * HID_ + d), acc);
        if (is_z) g_zw[row * HID_ + d] = acc;
        else      g_ew[row * HID_ + d] = acc;
        if (!is_z && row < 16) {
            const int i = row * HID_ + d;
            g_sinc[i] = b_out[0];
            g_cosc[i] = b_out[1];
        }
    }
}

// ---------------- fused MLP GEMM (CTA 256x128, 16 warps, warp 64x32, 3-stage) --
// MODE 0: middle/first layer (MODE 1 variant computes A in-stage)
// MODE 2: last layer; epilogue fuses w_out projection AND (last CTA per stripe)
//         the Fourier synthesis for that stripe's 2 batches.
template <int MODE>
__global__ void __launch_bounds__(NT_, 1) k_mma_gemm(int layer, int src, int dst,
                                                     const float* __restrict__ bias,
                                                     const float* __restrict__ w_out,
                                                     const float* __restrict__ tx,
                                                     float* __restrict__ outp) {
    extern __shared__ char smem[];
    const int tid = threadIdx.x;
    const int wid = tid >> 5;
    const int lane = tid & 31;
    const int wm = wid & 3;        // 4 warp-rows of 64
    const int wn = wid >> 2;       // 4 warp-cols of 32
    const int m0 = blockIdx.y * BM_;
    const int n0 = blockIdx.x * BN_;

    const __nv_bfloat16* __restrict__ Ahi  = g_ahi[src];
    const __nv_bfloat16* __restrict__ Alo  = g_alo[src];
    const __nv_bfloat16* __restrict__ Wthi = g_wthi[layer];
    const __nv_bfloat16* __restrict__ Wtlo = g_wtlo[layer];
    __nv_bfloat16* __restrict__ Dhi = g_ahi[dst];
    __nv_bfloat16* __restrict__ Dlo = g_alo[dst];

    const uint32_t smb = smem_u32(smem);

    auto stage_load = [&](int c) {
        const int k0 = c * KC_;
        const int buf = c % NSTAGE_;
        char* sb = smem + buf * STAGE_B;
        const uint32_t sbu = smb + buf * STAGE_B;
        if (MODE != 1) {
            #pragma unroll
            for (int i = 0; i < 4; i++) {           // A hi/lo: 2048 cp16
                const int idx = tid + i * NT_;
                const int t = idx >> 10;
                const int j = idx & 1023;
                const int r = j >> 2;
                const int c16 = j & 3;
                const uint32_t sm = sbu + (t ? OFF_AL : OFF_AH) + r * ROWB_ + c16 * 16;
                const __nv_bfloat16* gp = (t ? Alo : Ahi) + (size_t)(m0 + r) * HID_ + k0 + c16 * 8;
                cp16(sm, gp);
            }
        } else {
            // A = silu(zw[b] + ew[h]) split hi/lo: 256 rows x 32 k (2048 quads)
            #pragma unroll
            for (int i = 0; i < 4; i++) {
                const int idx = tid + i * NT_;
                const int r = idx >> 3;
                const int q = idx & 7;
                const int row = m0 + r;
                const int bb = row >> 7;
                const int hh = row & (NH_ - 1);
                const float4 zv = *(const float4*)(g_zw + bb * HID_ + k0 + q * 4);
                const float4 ev = *(const float4*)(g_ew + hh * HID_ + k0 + q * 4);
                split_store(sb + OFF_AH, sb + OFF_AL, r * ROWB_ + q * 8,
                            silu(zv.x + ev.x), silu(zv.y + ev.y),
                            silu(zv.z + ev.z), silu(zv.w + ev.w));
            }
        }
        #pragma unroll
        for (int i = 0; i < 2; i++) {               // B hi/lo: 1024 cp16
            const int idx = tid + i * NT_;
            const int t = idx >> 9;
            const int j = idx & 511;
            const int r = j >> 2;
            const int c16 = j & 3;
            const uint32_t sm = sbu + (t ? OFF_BL : OFF_BH) + r * ROWB_ + c16 * 16;
            const __nv_bfloat16* gp = (t ? Wtlo : Wthi) + (size_t)(n0 + r) * HID_ + k0 + c16 * 8;
            cp16(sm, gp);
        }
        cp_commit();
    };

    float acc[4][4][4];
    #pragma unroll
    for (int i = 0; i < 4; i++)
        #pragma unroll
        for (int j = 0; j < 4; j++)
            #pragma unroll
            for (int q = 0; q < 4; q++) acc[i][j][q] = 0.f;

    const int arow = wm * 64 + (lane & 15);
    const int acol = (lane >> 4) << 3;
    const int brow = wn * 32 + ((lane >> 4) & 1) * 8 + (lane & 7);
    const int bcol = ((lane >> 3) & 1) * 8;

    stage_load(0);

    for (int c = 0; c < NCH_; c++) {
        if (c + 1 < NCH_) {
            stage_load(c + 1);
            cp_wait<1>();
        } else {
            cp_wait<0>();
        }
        __syncthreads();   // single barrier per chunk (3-stage: no WAR hazard)

        const uint32_t sbu = smb + (c % NSTAGE_) * STAGE_B;
        const uint32_t aH = sbu + OFF_AH, aL = sbu + OFF_AL;
        const uint32_t bH = sbu + OFF_BH, bL = sbu + OFF_BL;

        #pragma unroll
        for (int ks = 0; ks < 2; ks++) {
            const int kc = ks * 16;
            uint32_t bh[8], bl[8];
            #pragma unroll
            for (int np = 0; np < 2; np++) {
                const uint32_t bo = (uint32_t)((brow + np * 16) * SPAD_ + bcol + kc) * 2;
                ldsm_x4(bh + np * 4, bH + bo);
                ldsm_x4(bl + np * 4, bL + bo);
            }
            #pragma unroll
            for (int mt = 0; mt < 4; mt++) {
                const uint32_t ao = (uint32_t)((arow + mt * 16) * SPAD_ + acol + kc) * 2;
                uint32_t ah[4], al[4];
                ldsm_x4(ah, aH + ao);
                ldsm_x4(al, aL + ao);
                #pragma unroll
                for (int nt = 0; nt < 4; nt++) mma_bf16(acc[mt][nt], ah, bh + nt * 2);
                #pragma unroll
                for (int nt = 0; nt < 4; nt++) mma_bf16(acc[mt][nt], ah, bl + nt * 2);
                #pragma unroll
                for (int nt = 0; nt < 4; nt++) mma_bf16(acc[mt][nt], al, bh + nt * 2);
            }
        }
    }

    const int g = lane >> 2;
    const int cpair = (lane & 3) * 2;

    if (MODE != 2) {
        #pragma unroll
        for (int mt = 0; mt < 4; mt++) {
            #pragma unroll
            for (int nt = 0; nt < 4; nt++) {
                const int row = m0 + wm * 64 + mt * 16 + g;
                const int col = n0 + wn * 32 + nt * 8 + cpair;
                const float b0 = __ldg(bias + col);
                const float b1 = __ldg(bias + col + 1);
                #pragma unroll
                for (int half = 0; half < 2; half++) {
                    const int r = row + half * 8;
                    const float v0 = silu(acc[mt][nt][half * 2 + 0] + b0);
                    const float v1 = silu(acc[mt][nt][half * 2 + 1] + b1);
                    const __nv_bfloat16 h0 = __float2bfloat16(v0);
                    const __nv_bfloat16 h1 = __float2bfloat16(v1);
                    const __nv_bfloat16 l0 = __float2bfloat16(v0 - __bfloat162float(h0));
                    const __nv_bfloat16 l1 = __float2bfloat16(v1 - __bfloat162float(h1));
                    __nv_bfloat162 ph, pl;
                    ph.x = h0; ph.y = h1;
                    pl.x = l0; pl.y = l1;
                    *(__nv_bfloat162*)(Dhi + (size_t)r * HID_ + col) = ph;
                    *(__nv_bfloat162*)(Dlo + (size_t)r * HID_ + col) = pl;
                }
            }
        }
    } else {
        // fused coeff projection
        #pragma unroll
        for (int mt = 0; mt < 4; mt++) {
            #pragma unroll
            for (int half = 0; half < 2; half++) {
                float s = 0.f, cs = 0.f;
                #pragma unroll
                for (int nt = 0; nt < 4; nt++) {
                    const int col = n0 + wn * 32 + nt * 8 + cpair;
                    const float b0 = __ldg(bias + col);
                    const float b1 = __ldg(bias + col + 1);
                    const float v0 = silu(acc[mt][nt][half * 2 + 0] + b0);
                    const float v1 = silu(acc[mt][nt][half * 2 + 1] + b1);
                    s  = fmaf(v0, __ldg(w_out + 2 * col + 0), s);
                    cs = fmaf(v0, __ldg(w_out + 2 * col + 1), cs);
                    s  = fmaf(v1, __ldg(w_out + 2 * col + 2), s);
                    cs = fmaf(v1, __ldg(w_out + 2 * col + 3), cs);
                }
                s  += __shfl_xor_sync(0xffffffffu, s, 1);
                s  += __shfl_xor_sync(0xffffffffu, s, 2);
                cs += __shfl_xor_sync(0xffffffffu, cs, 1);
                cs += __shfl_xor_sync(0xffffffffu, cs, 2);
                if ((lane & 3) == 0) {
                    const int row = m0 + wm * 64 + mt * 16 + g + half * 8;
                    atomicAdd(&g_sinc[row], s);
                    atomicAdd(&g_cosc[row], cs);
                }
            }
        }

        // ---- last n-tile CTA of this m-stripe runs synthesis for its 2 batches ----
        __threadfence();
        __syncthreads();
        __shared__ int s_prev;
        if (tid == 0) s_prev = atomicAdd(&g_cnt[blockIdx.y], 1);
        __syncthreads();
        if (s_prev == gridDim.x - 1) {
            // coeffs for rows m0..m0+255 (= batches 2*blockIdx.y, +1)
            float* scc = (float*)smem;            // [256] sin coeffs
            float* ccc = (float*)smem + 256;      // [256] cos coeffs
            if (tid < 256) {
                scc[tid] = __ldcg(&g_sinc[m0 + tid]);
                ccc[tid] = __ldcg(&g_cosc[m0 + tid]);
            }
            __syncthreads();
            const int b0 = blockIdx.y * 2;
            for (int i = tid; i < 2 * S_; i += NT_) {
                const int bloc = i >> 12;             // 0/1
                const int sI = i & (S_ - 1);
                const float* sc = scc + bloc * NH_;
                const float* cc = ccc + bloc * NH_;
                const float xv = tx[(b0 + bloc) * S_ + sI];
                const float th = 6.28318530717958647692f * xv;
                float s1, c1;
                sincosf(th, &s1, &c1);
                const float c2 = c1 * c1 - s1 * s1;
                const float s2 = 2.f * s1 * c1;
                float ca = c1, sa = s1;
                float cb = c2, sb = s2;
                float a0 = fmaf(cc[0], ca, sc[0] * sa);
                float a1 = fmaf(cc[1], cb, sc[1] * sb);
                #pragma unroll 4
                for (int hh = 1; hh < 64; hh++) {
                    const float can = ca * c2 - sa * s2;
                    const float san = sa * c2 + ca * s2;
                    ca = can; sa = san;
                    const float cbn = cb * c2 - sb * s2;
                    const float sbn = sb * c2 + cb * s2;
                    cb = cbn; sb = sbn;
                    a0 = fmaf(cc[2 * hh], ca, a0);
                    a0 = fmaf(sc[2 * hh], sa, a0);
                    a1 = fmaf(cc[2 * hh + 1], cb, a1);
                    a1 = fmaf(sc[2 * hh + 1], sb, a1);
                }
                outp[(b0 + bloc) * S_ + sI] = a0 + a1;
            }
        }
    }
}

// ---------------- launcher ----------------
extern "C" void kernel_launch(void* const* d_in, const int* in_sizes, int n_in,
                              void* d_out, int out_size) {
    const float* target_x = (const float*)d_in[0];
    const float* z        = (const float*)d_in[1];
    /* d_in[2] = x, unused by the reference */
    const float* emb      = (const float*)d_in[3];
    const float* w_in     = (const float*)d_in[4];
    const float* b_in     = (const float*)d_in[5];
    const float* w_h      = (const float*)d_in[6];
    const float* b_h      = (const float*)d_in[7];
    const float* w_out    = (const float*)d_in[8];
    const float* b_out    = (const float*)d_in[9];
    float* out = (float*)d_out;

    cudaFuncSetAttribute(k_mma_gemm<0>, cudaFuncAttributeMaxDynamicSharedMemorySize, SMEM_DYN);
    cudaFuncSetAttribute(k_mma_gemm<1>, cudaFuncAttributeMaxDynamicSharedMemorySize, SMEM_DYN);
    cudaFuncSetAttribute(k_mma_gemm<2>, cudaFuncAttributeMaxDynamicSharedMemorySize, SMEM_DYN);

    k_prep<<<1152, 256>>>(w_h, z, emb, w_in, b_in, b_out);

    k_mma_gemm<1><<<dim3(HID_ / BN_, M_ / BM_), NT_, SMEM_DYN>>>(0, 0, 0, b_h + 0 * HID_,
                                                                 w_out, nullptr, nullptr);
    k_mma_gemm<0><<<dim3(HID_ / BN_, M_ / BM_), NT_, SMEM_DYN>>>(1, 0, 1, b_h + 1 * HID_,
                                                                 w_out, nullptr, nullptr);
    k_mma_gemm<2><<<dim3(HID_ / BN_, M_ / BM_), NT_, SMEM_DYN>>>(2, 1, 0, b_h + 2 * HID_,
                                                                 w_out, target_x, out);
}

// round 15
// speedup vs baseline: 1.2581x; 1.1653x over previous
#include <cuda_runtime.h>
#include <cuda_bf16.h>
#include <math.h>
#include <stdint.h>

#define B_    64
#define S_    4096
#define E_    266
#define HID_  512
#define NH_   128
#define M_    (B_ * NH_)   /* 8192 rows */
#define KC_   32           /* K chunk */
#define NCH_  (HID_ / KC_) /* 16 chunks */
#define SPAD_ 40           /* padded smem row stride in bf16 */
#define BM_   256          /* CTA tile M */
#define BN_   128          /* CTA tile N */
#define NT_   512          /* 16 warps, warp grid 4x4, warp tile 64x32 */
#define NCTA_ ((M_ / BM_) * (HID_ / BN_))   /* 128 CTAs, all resident */

#define ROWB_     (SPAD_ * 2)                       /* 80 B */
#define OFF_AH    0
#define OFF_AL    (BM_ * ROWB_)                     /* 20480 */
#define OFF_BH    (2 * BM_ * ROWB_)                 /* 40960 */
#define OFF_BL    (2 * BM_ * ROWB_ + BN_ * ROWB_)   /* 51200 */
#define STAGE_B   (2 * BM_ * ROWB_ + 2 * BN_ * ROWB_) /* 61440 */
#define NSTAGE_   3
#define SMEM_DYN  (NSTAGE_ * STAGE_B)               /* 184320 */

__device__ __align__(16) __nv_bfloat16 g_ahi[2][M_ * HID_];
__device__ __align__(16) __nv_bfloat16 g_alo[2][M_ * HID_];
__device__ __align__(16) __nv_bfloat16 g_wthi[3][HID_ * HID_];
__device__ __align__(16) __nv_bfloat16 g_wtlo[3][HID_ * HID_];
__device__ float g_zw[B_ * HID_];
__device__ float g_ew[NH_ * HID_];
__device__ float g_sinc[M_];
__device__ float g_cosc[M_];
__device__ int   g_bar;           /* grid-wide layer barrier */

__device__ __forceinline__ float silu(float v) {
    return __fdividef(v, 1.0f + __expf(-v));
}
__device__ __forceinline__ uint32_t smem_u32(const void* p) {
    uint32_t a;
    asm("{ .reg .u64 t; cvta.to.shared.u64 t, %1; cvt.u32.u64 %0, t; }" : "=r"(a) : "l"(p));
    return a;
}
__device__ __forceinline__ void cp16(uint32_t sm, const void* g) {
    asm volatile("cp.async.cg.shared.global [%0], [%1], 16;" :: "r"(sm), "l"(g));
}
__device__ __forceinline__ void cp_commit() {
    asm volatile("cp.async.commit_group;" ::: "memory");
}
template <int N>
__device__ __forceinline__ void cp_wait() {
    asm volatile("cp.async.wait_group %0;" :: "n"(N) : "memory");
}
__device__ __forceinline__ void ldsm_x4(uint32_t* r, uint32_t addr) {
    asm volatile("ldmatrix.sync.aligned.m8n8.x4.shared.b16 {%0,%1,%2,%3}, [%4];"
                 : "=r"(r[0]), "=r"(r[1]), "=r"(r[2]), "=r"(r[3]) : "r"(addr));
}
__device__ __forceinline__ void mma_bf16(float* c, const uint32_t* a, const uint32_t* b) {
    asm volatile("mma.sync.aligned.m16n8k16.row.col.f32.bf16.bf16.f32 "
                 "{%0,%1,%2,%3}, {%4,%5,%6,%7}, {%8,%9}, {%0,%1,%2,%3};"
                 : "+f"(c[0]), "+f"(c[1]), "+f"(c[2]), "+f"(c[3])
                 : "r"(a[0]), "r"(a[1]), "r"(a[2]), "r"(a[3]), "r"(b[0]), "r"(b[1]));
}
__device__ __forceinline__ void split_store(char* sm_hi, char* sm_lo, int off,
                                            float v0, float v1, float v2, float v3) {
    const __nv_bfloat16 h0 = __float2bfloat16(v0), h1 = __float2bfloat16(v1);
    const __nv_bfloat16 h2 = __float2bfloat16(v2), h3 = __float2bfloat16(v3);
    const __nv_bfloat16 l0 = __float2bfloat16(v0 - __bfloat162float(h0));
    const __nv_bfloat16 l1 = __float2bfloat16(v1 - __bfloat162float(h1));
    const __nv_bfloat16 l2 = __float2bfloat16(v2 - __bfloat162float(h2));
    const __nv_bfloat16 l3 = __float2bfloat16(v3 - __bfloat162float(h3));
    ushort4 ph, pl;
    ph.x = __bfloat16_as_ushort(h0); ph.y = __bfloat16_as_ushort(h1);
    ph.z = __bfloat16_as_ushort(h2); ph.w = __bfloat16_as_ushort(h3);
    pl.x = __bfloat16_as_ushort(l0); pl.y = __bfloat16_as_ushort(l1);
    pl.z = __bfloat16_as_ushort(l2); pl.w = __bfloat16_as_ushort(l3);
    *(ushort4*)(sm_hi + off) = ph;
    *(ushort4*)(sm_lo + off) = pl;
}

// ---------------- fused prep: weight transpose/split + zw/ew(8-row) + seeds ----
// blocks [0,768): weight transpose+split; blocks [768,816): zw/ew, seeds, barrier reset
__global__ void k_prep(const float* __restrict__ w_h,
                       const float* __restrict__ z, const float* __restrict__ emb,
                       const float* __restrict__ w_in, const float* __restrict__ b_in,
                       const float* __restrict__ b_out) {
    if (blockIdx.x < 768) {
        __shared__ float t[32][33];
        const int idx = blockIdx.x;
        const int l = idx >> 8;
        const int rem = idx & 255;
        const int k0 = (rem >> 4) * 32, n0 = (rem & 15) * 32;
        const int tx = threadIdx.x & 31, ty = threadIdx.x >> 5;
        const float* W = w_h + (size_t)l * HID_ * HID_;
        for (int i = ty; i < 32; i += 8)
            t[i][tx] = W[(size_t)(k0 + i) * HID_ + n0 + tx];
        __syncthreads();
        for (int i = ty; i < 32; i += 8) {
            const float v = t[tx][i];
            const __nv_bfloat16 hi = __float2bfloat16(v);
            const __nv_bfloat16 lo = __float2bfloat16(v - __bfloat162float(hi));
            g_wthi[l][(size_t)(n0 + i) * HID_ + k0 + tx] = hi;
            g_wtlo[l][(size_t)(n0 + i) * HID_ + k0 + tx] = lo;
        }
    } else {
        __shared__ float vr[8][E_];                  /* 8 rows x 266 */
        const int idx2 = blockIdx.x - 768;           /* 0..47 */
        if (idx2 == 0 && threadIdx.x == 0) g_bar = 0;
        const int dblk = idx2 & 1;                   /* column half */
        const int grp = idx2 >> 1;                   /* 0..23: 0-7=z, 8-23=emb */
        const bool is_z = (grp < 8);
        const int r0 = is_z ? grp * 8 : (grp - 8) * 8;
        const float* src = (is_z ? z : emb) + (size_t)r0 * E_;
        for (int i = threadIdx.x; i < 8 * E_; i += blockDim.x)
            vr[i / E_][i % E_] = src[i];
        __syncthreads();
        const int d = dblk * 256 + threadIdx.x;
        float acc[8];
        const float binit = is_z ? 0.f : b_in[d];
        #pragma unroll
        for (int r = 0; r < 8; r++) acc[r] = binit;
        for (int e = 0; e < E_; e++) {
            const float w = __ldg(w_in + e * HID_ + d);
            #pragma unroll
            for (int r = 0; r < 8; r++) acc[r] = fmaf(vr[r][e], w, acc[r]);
        }
        float* dst = (is_z ? g_zw : g_ew) + (size_t)r0 * HID_ + d;
        #pragma unroll
        for (int r = 0; r < 8; r++) dst[r * HID_] = acc[r];
        // seed coeff accumulators (48 blocks x 256 threads = 12288 >= 8192)
        const int sid = idx2 * 256 + threadIdx.x;
        if (sid < M_) {
            g_sinc[sid] = b_out[0];
            g_cosc[sid] = b_out[1];
        }
    }
}

// ---------------- grid-wide barrier (all NCTA_ CTAs resident) ----------------
__device__ __forceinline__ void grid_bar(int target, int tid) {
    __threadfence();
    __syncthreads();
    if (tid == 0) {
        atomicAdd(&g_bar, 1);
        while (*((volatile int*)&g_bar) < target) { }
    }
    __syncthreads();
    __threadfence();
}

// ---------------- one GEMM layer (R12 inner loop, verbatim) ----------------
// MODE 1: A computed in-stage from zw/ew. MODE 0: A from g_a*[src], D to g_a*[dst].
// MODE 2: epilogue fused with w_out projection -> atomics.
template <int MODE>
__device__ __forceinline__ void run_layer(
    int layer, int src, int dst,
    const float* __restrict__ bias, const float* __restrict__ w_out,
    char* smem, uint32_t smb, int tid, int lane, int wm, int wn, int m0, int n0) {

    const __nv_bfloat16* __restrict__ Ahi  = g_ahi[src];
    const __nv_bfloat16* __restrict__ Alo  = g_alo[src];
    const __nv_bfloat16* __restrict__ Wthi = g_wthi[layer];
    const __nv_bfloat16* __restrict__ Wtlo = g_wtlo[layer];
    __nv_bfloat16* __restrict__ Dhi = g_ahi[dst];
    __nv_bfloat16* __restrict__ Dlo = g_alo[dst];

    auto stage_load = [&](int c) {
        const int k0 = c * KC_;
        const int buf = c % NSTAGE_;
        char* sb = smem + buf * STAGE_B;
        const uint32_t sbu = smb + buf * STAGE_B;
        if (MODE != 1) {
            #pragma unroll
            for (int i = 0; i < 4; i++) {           // A hi/lo: 2048 cp16
                const int idx = tid + i * NT_;
                const int t = idx >> 10;
                const int j = idx & 1023;
                const int r = j >> 2;
                const int c16 = j & 3;
                const uint32_t sm = sbu + (t ? OFF_AL : OFF_AH) + r * ROWB_ + c16 * 16;
                const __nv_bfloat16* gp = (t ? Alo : Ahi) + (size_t)(m0 + r) * HID_ + k0 + c16 * 8;
                cp16(sm, gp);
            }
        } else {
            #pragma unroll
            for (int i = 0; i < 4; i++) {           // A = silu(zw+ew) split
                const int idx = tid + i * NT_;
                const int r = idx >> 3;
                const int q = idx & 7;
                const int row = m0 + r;
                const int bb = row >> 7;
                const int hh = row & (NH_ - 1);
                const float4 zv = *(const float4*)(g_zw + bb * HID_ + k0 + q * 4);
                const float4 ev = *(const float4*)(g_ew + hh * HID_ + k0 + q * 4);
                split_store(sb + OFF_AH, sb + OFF_AL, r * ROWB_ + q * 8,
                            silu(zv.x + ev.x), silu(zv.y + ev.y),
                            silu(zv.z + ev.z), silu(zv.w + ev.w));
            }
        }
        #pragma unroll
        for (int i = 0; i < 2; i++) {               // B hi/lo: 1024 cp16
            const int idx = tid + i * NT_;
            const int t = idx >> 9;
            const int j = idx & 511;
            const int r = j >> 2;
            const int c16 = j & 3;
            const uint32_t sm = sbu + (t ? OFF_BL : OFF_BH) + r * ROWB_ + c16 * 16;
            const __nv_bfloat16* gp = (t ? Wtlo : Wthi) + (size_t)(n0 + r) * HID_ + k0 + c16 * 8;
            cp16(sm, gp);
        }
        cp_commit();
    };

    float acc[4][4][4];
    #pragma unroll
    for (int i = 0; i < 4; i++)
        #pragma unroll
        for (int j = 0; j < 4; j++)
            #pragma unroll
            for (int q = 0; q < 4; q++) acc[i][j][q] = 0.f;

    const int arow = wm * 64 + (lane & 15);
    const int acol = (lane >> 4) << 3;
    const int brow = wn * 32 + ((lane >> 4) & 1) * 8 + (lane & 7);
    const int bcol = ((lane >> 3) & 1) * 8;

    stage_load(0);

    for (int c = 0; c < NCH_; c++) {
        if (c + 1 < NCH_) {
            stage_load(c + 1);
            cp_wait<1>();
        } else {
            cp_wait<0>();
        }
        __syncthreads();

        const uint32_t sbu = smb + (c % NSTAGE_) * STAGE_B;
        const uint32_t aH = sbu + OFF_AH, aL = sbu + OFF_AL;
        const uint32_t bH = sbu + OFF_BH, bL = sbu + OFF_BL;

        #pragma unroll
        for (int ks = 0; ks < 2; ks++) {
            const int kc = ks * 16;
            uint32_t bh[8], bl[8];
            #pragma unroll
            for (int np = 0; np < 2; np++) {
                const uint32_t bo = (uint32_t)((brow + np * 16) * SPAD_ + bcol + kc) * 2;
                ldsm_x4(bh + np * 4, bH + bo);
                ldsm_x4(bl + np * 4, bL + bo);
            }
            #pragma unroll
            for (int mt = 0; mt < 4; mt++) {
                const uint32_t ao = (uint32_t)((arow + mt * 16) * SPAD_ + acol + kc) * 2;
                uint32_t ah[4], al[4];
                ldsm_x4(ah, aH + ao);
                ldsm_x4(al, aL + ao);
                #pragma unroll
                for (int nt = 0; nt < 4; nt++) mma_bf16(acc[mt][nt], ah, bh + nt * 2);
                #pragma unroll
                for (int nt = 0; nt < 4; nt++) mma_bf16(acc[mt][nt], ah, bl + nt * 2);
                #pragma unroll
                for (int nt = 0; nt < 4; nt++) mma_bf16(acc[mt][nt], al, bh + nt * 2);
            }
        }
    }

    const int g = lane >> 2;
    const int cpair = (lane & 3) * 2;

    if (MODE != 2) {
        #pragma unroll
        for (int mt = 0; mt < 4; mt++) {
            #pragma unroll
            for (int nt = 0; nt < 4; nt++) {
                const int row = m0 + wm * 64 + mt * 16 + g;
                const int col = n0 + wn * 32 + nt * 8 + cpair;
                const float b0 = __ldg(bias + col);
                const float b1 = __ldg(bias + col + 1);
                #pragma unroll
                for (int half = 0; half < 2; half++) {
                    const int r = row + half * 8;
                    const float v0 = silu(acc[mt][nt][half * 2 + 0] + b0);
                    const float v1 = silu(acc[mt][nt][half * 2 + 1] + b1);
                    const __nv_bfloat16 h0 = __float2bfloat16(v0);
                    const __nv_bfloat16 h1 = __float2bfloat16(v1);
                    const __nv_bfloat16 l0 = __float2bfloat16(v0 - __bfloat162float(h0));
                    const __nv_bfloat16 l1 = __float2bfloat16(v1 - __bfloat162float(h1));
                    __nv_bfloat162 ph, pl;
                    ph.x = h0; ph.y = h1;
                    pl.x = l0; pl.y = l1;
                    *(__nv_bfloat162*)(Dhi + (size_t)r * HID_ + col) = ph;
                    *(__nv_bfloat162*)(Dlo + (size_t)r * HID_ + col) = pl;
                }
            }
        }
    } else {
        #pragma unroll
        for (int mt = 0; mt < 4; mt++) {
            #pragma unroll
            for (int half = 0; half < 2; half++) {
                float s = 0.f, cs = 0.f;
                #pragma unroll
                for (int nt = 0; nt < 4; nt++) {
                    const int col = n0 + wn * 32 + nt * 8 + cpair;
                    const float b0 = __ldg(bias + col);
                    const float b1 = __ldg(bias + col + 1);
                    const float v0 = silu(acc[mt][nt][half * 2 + 0] + b0);
                    const float v1 = silu(acc[mt][nt][half * 2 + 1] + b1);
                    s  = fmaf(v0, __ldg(w_out + 2 * col + 0), s);
                    cs = fmaf(v0, __ldg(w_out + 2 * col + 1), cs);
                    s  = fmaf(v1, __ldg(w_out + 2 * col + 2), s);
                    cs = fmaf(v1, __ldg(w_out + 2 * col + 3), cs);
                }
                s  += __shfl_xor_sync(0xffffffffu, s, 1);
                s  += __shfl_xor_sync(0xffffffffu, s, 2);
                cs += __shfl_xor_sync(0xffffffffu, cs, 1);
                cs += __shfl_xor_sync(0xffffffffu, cs, 2);
                if ((lane & 3) == 0) {
                    const int row = m0 + wm * 64 + mt * 16 + g + half * 8;
                    atomicAdd(&g_sinc[row], s);
                    atomicAdd(&g_cosc[row], cs);
                }
            }
        }
    }
}

// ---------------- persistent 3-layer MLP kernel ----------------
__global__ void __launch_bounds__(NT_, 1) k_mlp(const float* __restrict__ b_h,
                                                const float* __restrict__ w_out) {
    extern __shared__ char smem[];
    const uint32_t smb = smem_u32(smem);
    const int tid = threadIdx.x;
    const int lane = tid & 31;
    const int wid = tid >> 5;
    const int wm = wid & 3;
    const int wn = wid >> 2;
    const int m0 = blockIdx.y * BM_;
    const int n0 = blockIdx.x * BN_;

    run_layer<1>(0, 0, 0, b_h + 0 * HID_, w_out, smem, smb, tid, lane, wm, wn, m0, n0);
    grid_bar(NCTA_, tid);
    run_layer<0>(1, 0, 1, b_h + 1 * HID_, w_out, smem, smb, tid, lane, wm, wn, m0, n0);
    grid_bar(2 * NCTA_, tid);
    run_layer<2>(2, 1, 0, b_h + 2 * HID_, w_out, smem, smb, tid, lane, wm, wn, m0, n0);
}

// ---------------- synthesis: 2-chain integer-frequency recurrence ----------------
__global__ void k_synth(const float* __restrict__ tx, float* __restrict__ out) {
    __shared__ float sc[NH_], cc[NH_];
    const int b = blockIdx.y;
    if (threadIdx.x < NH_) {
        sc[threadIdx.x] = g_sinc[b * NH_ + threadIdx.x];
        cc[threadIdx.x] = g_cosc[b * NH_ + threadIdx.x];
    }
    __syncthreads();
    const int sI = blockIdx.x * blockDim.x + threadIdx.x;
    const float xv = tx[b * S_ + sI];
    const float th = 6.28318530717958647692f * xv;
    float s1, c1;
    sincosf(th, &s1, &c1);
    const float c2 = c1 * c1 - s1 * s1;
    const float s2 = 2.f * s1 * c1;
    float ca = c1, sa = s1;
    float cb = c2, sb = s2;
    float acc0 = fmaf(cc[0], ca, sc[0] * sa);
    float acc1 = fmaf(cc[1], cb, sc[1] * sb);
    #pragma unroll 4
    for (int i = 1; i < 64; i++) {
        const float can = ca * c2 - sa * s2;
        const float san = sa * c2 + ca * s2;
        ca = can; sa = san;
        const float cbn = cb * c2 - sb * s2;
        const float sbn = sb * c2 + cb * s2;
        cb = cbn; sb = sbn;
        acc0 = fmaf(cc[2 * i], ca, acc0);
        acc0 = fmaf(sc[2 * i], sa, acc0);
        acc1 = fmaf(cc[2 * i + 1], cb, acc1);
        acc1 = fmaf(sc[2 * i + 1], sb, acc1);
    }
    out[b * S_ + sI] = acc0 + acc1;
}

// ---------------- launcher ----------------
extern "C" void kernel_launch(void* const* d_in, const int* in_sizes, int n_in,
                              void* d_out, int out_size) {
    const float* target_x = (const float*)d_in[0];
    const float* z        = (const float*)d_in[1];
    /* d_in[2] = x, unused by the reference */
    const float* emb      = (const float*)d_in[3];
    const float* w_in     = (const float*)d_in[4];
    const float* b_in     = (const float*)d_in[5];
    const float* w_h      = (const float*)d_in[6];
    const float* b_h      = (const float*)d_in[7];
    const float* w_out    = (const float*)d_in[8];
    const float* b_out    = (const float*)d_in[9];
    float* out = (float*)d_out;

    cudaFuncSetAttribute(k_mlp, cudaFuncAttributeMaxDynamicSharedMemorySize, SMEM_DYN);

    k_prep<<<816, 256>>>(w_h, z, emb, w_in, b_in, b_out);
    k_mlp<<<dim3(HID_ / BN_, M_ / BM_), NT_, SMEM_DYN>>>(b_h, w_out);
    k_synth<<<dim3(S_ / 256, B_), 256>>>(target_x, out);
}